// round 8
// baseline (speedup 1.0000x reference)
#include <cuda_runtime.h>
#include <stdint.h>

// Problem shape (fixed by the dataset)
#define N_DST 8192
#define N_SRC 32768
#define HW    2048              // 64*32 floats per row
#define ROW4  (HW / 4)          // 512 float4 per row
#define NSCAT  (N_SRC / 256)    // 128 scatter blocks
#define BUCKET_CAP 64           // Poisson(4): P(overflow) ~ 1e-60

// Scratch in __device__ globals (no allocation allowed anywhere).
// INVARIANT: g_counts is all-zero at every kernel_launch entry — it is
// zero-initialized at module load, and every gather block zeroes its own
// count after reading it (race-free: count[d] is touched only by block d).
__device__ int g_counts[N_DST];
__device__ int g_bucket[N_DST * BUCKET_CAP];   // 2 MB

// ---------------------------------------------------------------------------
// Pass 0: bucket scatter. No zeroing needed (see invariant above), so no
// memset node and no inter-block barrier — just detect + append.
//
// Dtype detect per 256-word window: word i is in-bounds for both int32[32768]
// and int64[32768]. If ALL odd words in the window are zero -> little-endian
// int64 (high halves of values 0..8191); for int32 data P(128 random indices
// all zero) = 8192^-128 ~ 0. The int64 load is only issued when is64 holds.
__global__ void __launch_bounds__(256) scatter_kernel(const int* __restrict__ idxw) {
    __shared__ int s_any;
    const int tid = threadIdx.x;
    const int i   = blockIdx.x * 256 + tid;    // source element id 0..32767

    if (tid == 0) s_any = 0;
    int w = idxw[i];
    __syncthreads();
    bool odd_nz = (i & 1) && (w != 0);
    unsigned m = __ballot_sync(0xffffffffu, odd_nz);
    if ((tid & 31) == 0 && m) atomicOr(&s_any, 1);
    __syncthreads();
    bool is64 = (s_any == 0);
    int d = is64 ? (int)((const long long*)idxw)[i] : w;

    int pos = atomicAdd(&g_counts[d], 1);
    if (pos < BUCKET_CAP)
        g_bucket[d * BUCKET_CAP + pos] = i;
}

// ---------------------------------------------------------------------------
// Pass 1: gather-max. One block per dest row, 512 threads, one float4 each
// -> every t-row read is a fully coalesced 128B-sector stream and k is
// block-uniform. After reading its count, the block zeroes it (restores the
// all-zero invariant for the next replay).
__global__ void __launch_bounds__(512) gather_kernel(
    const float4* __restrict__ x,
    const float4* __restrict__ t,
    float4* __restrict__ out)
{
    const int d = blockIdx.x;             // dest row
    const int c = threadIdx.x;            // float4 column 0..511
    const long gid = (long)d * ROW4 + c;

    float4 v = x[gid];

    int k = g_counts[d];                  // broadcast read, all threads
    __syncthreads();                      // all reads done before the zero
    if (c == 0) g_counts[d] = 0;          // restore invariant (only block d
                                          // ever touches count[d])
    if (k > BUCKET_CAP) k = BUCKET_CAP;
    const int* bucket = &g_bucket[d * BUCKET_CAP];

    int s = 0;
    for (; s + 4 <= k; s += 4) {
        int i0 = bucket[s + 0];
        int i1 = bucket[s + 1];
        int i2 = bucket[s + 2];
        int i3 = bucket[s + 3];
        float4 t0 = __ldcs(&t[(long)i0 * ROW4 + c]);
        float4 t1 = __ldcs(&t[(long)i1 * ROW4 + c]);
        float4 t2 = __ldcs(&t[(long)i2 * ROW4 + c]);
        float4 t3 = __ldcs(&t[(long)i3 * ROW4 + c]);
        v.x = fmaxf(fmaxf(fmaxf(v.x, t0.x), fmaxf(t1.x, t2.x)), t3.x);
        v.y = fmaxf(fmaxf(fmaxf(v.y, t0.y), fmaxf(t1.y, t2.y)), t3.y);
        v.z = fmaxf(fmaxf(fmaxf(v.z, t0.z), fmaxf(t1.z, t2.z)), t3.z);
        v.w = fmaxf(fmaxf(fmaxf(v.w, t0.w), fmaxf(t1.w, t2.w)), t3.w);
    }
    for (; s < k; s++) {
        int sid = bucket[s];
        float4 tv = __ldcs(&t[(long)sid * ROW4 + c]);
        v.x = fmaxf(v.x, tv.x);
        v.y = fmaxf(v.y, tv.y);
        v.z = fmaxf(v.z, tv.z);
        v.w = fmaxf(v.w, tv.w);
    }

    __stcs(&out[gid], v);
}

// ---------------------------------------------------------------------------
extern "C" void kernel_launch(void* const* d_in, const int* in_sizes, int n_in,
                              void* d_out, int out_size) {
    // Identify inputs by element count, not position.
    const float4* x = 0;
    const float4* t = 0;
    const void*   idx = 0;
    for (int i = 0; i < n_in; i++) {
        long long sz = in_sizes[i];
        if (sz == (long long)N_DST * HW)      x   = (const float4*)d_in[i];
        else if (sz == (long long)N_SRC * HW) t   = (const float4*)d_in[i];
        else if (sz == N_SRC)                 idx = d_in[i];
    }
    float4* out = (float4*)d_out;
    (void)out_size;

    scatter_kernel<<<NSCAT, 256>>>((const int*)idx);
    gather_kernel<<<N_DST, 512>>>(x, t, out);
}